// round 5
// baseline (speedup 1.0000x reference)
#include <cuda_runtime.h>

// Chen's relation signature combine. DIM=8, DEPTH=4.
// flat = 8 + 64 + 512 + 4096 = 4680. Levels: L1@0(8) L2@8(64) L3@72(512) L4@584(4096).
//
// out_L1    = a1 + b1
// out_L2[t] = a2[t]+b2[t] + a1[t/8]*b1[t%8]
// out_L3[t] = a3[t]+b3[t] + a1[t/64]*b2[t%64] + a2[t/8]*b1[t%8]
// out_L4[t] = a4[t]+b4[t] + a1[t/512]*b3[t%512] + a2[t/64]*b2[t%64] + a3[t/8]*b1[t%8]
//
// Cross-term operands all live in the 584-float prefix -> smem.
// Prefix outputs (first 146 float4s) are computed from the staging registers.
// The remaining 1024 float4s are exactly 4 branch-free all-L4 iterations.

#define FLAT 4680
#define NV4  1170
#define PREF 584
#define NPV4 146
#define NTHREADS 256

__global__ __launch_bounds__(NTHREADS)
void sig_combine_kernel(const float* __restrict__ g1,
                        const float* __restrict__ g2,
                        float* __restrict__ gout)
{
    __shared__ __align__(16) float a[PREF];
    __shared__ __align__(16) float b[PREF];

    const int row = blockIdx.x;
    const int tid = threadIdx.x;

    const float4* g1v = reinterpret_cast<const float4*>(g1 + (size_t)row * FLAT);
    const float4* g2v = reinterpret_cast<const float4*>(g2 + (size_t)row * FLAT);
    float4* outv = reinterpret_cast<float4*>(gout + (size_t)row * FLAT);

    // Stage prefixes (levels 1..3); keep register copies for the additive terms.
    float4 pa, pb;
    if (tid < NPV4) {
        pa = g1v[tid];
        pb = g2v[tid];
        reinterpret_cast<float4*>(a)[tid] = pa;
        reinterpret_cast<float4*>(b)[tid] = pb;
    }
    __syncthreads();

    // ---- Prefix outputs: vectors 0..145, additive terms already in regs ----
    if (tid < NPV4) {
        const int base = tid * 4;
        float4 r;
        float* rp = &r.x;
        const float* ap = &pa.x;
        const float* bp = &pb.x;

        if (base >= 72) {            // Level 3: t in [0,512)
            #pragma unroll
            for (int e = 0; e < 4; e++) {
                int t = base + e - 72;
                rp[e] = ap[e] + bp[e]
                      + a[t >> 6] * b[8 + (t & 63)]
                      + a[8 + (t >> 3)] * b[t & 7];
            }
        } else if (base >= 8) {      // Level 2: t in [0,64)
            #pragma unroll
            for (int e = 0; e < 4; e++) {
                int t = base + e - 8;
                rp[e] = ap[e] + bp[e] + a[t >> 3] * b[t & 7];
            }
        } else {                     // Level 1
            #pragma unroll
            for (int e = 0; e < 4; e++) rp[e] = ap[e] + bp[e];
        }
        outv[tid] = r;
    }

    // ---- Level-4 bulk: vectors 146..1169 = 4 exact full-width iterations ----
    // u in [0,1024), t0 = 4u. Across e=0..3: t0>>9, t0>>6, t0>>3 constant
    // (t0 % 4 == 0 and the 4-range never crosses an 8/64/512 boundary);
    // the b-side reads are aligned contiguous float4s.
    #pragma unroll
    for (int k = 0; k < 4; k++) {
        const int u  = k * NTHREADS + tid;      // 0..1023
        const int t0 = u * 4;
        const int v  = NPV4 + u;

        float4 va = g1v[v];
        float4 vb = g2v[v];

        const float a1 = a[t0 >> 9];
        const float a2 = a[8 + (t0 >> 6)];
        const float a3 = a[72 + (t0 >> 3)];
        const float4 b3 = *reinterpret_cast<const float4*>(&b[72 + (t0 & 511)]);
        const float4 b2 = *reinterpret_cast<const float4*>(&b[8 + (t0 & 63)]);
        const float4 b1 = *reinterpret_cast<const float4*>(&b[t0 & 7]);

        float4 r;
        r.x = va.x + vb.x + a1 * b3.x + a2 * b2.x + a3 * b1.x;
        r.y = va.y + vb.y + a1 * b3.y + a2 * b2.y + a3 * b1.y;
        r.z = va.z + vb.z + a1 * b3.z + a2 * b2.z + a3 * b1.z;
        r.w = va.w + vb.w + a1 * b3.w + a2 * b2.w + a3 * b1.w;

        outv[v] = r;
    }
}

extern "C" void kernel_launch(void* const* d_in, const int* in_sizes, int n_in,
                              void* d_out, int out_size)
{
    const float* s1 = (const float*)d_in[0];
    const float* s2 = (const float*)d_in[1];
    float* out = (float*)d_out;

    const int B = in_sizes[0] / FLAT;   // 16384
    sig_combine_kernel<<<B, NTHREADS>>>(s1, s2, out);
}